// round 3
// baseline (speedup 1.0000x reference)
#include <cuda_runtime.h>

// out[b,q,d] = sum_k values[b,k,d]  (softmax over singleton axis == 1;
// queries/keys/w_score are dead code). B=4, Q=512, K=512, F=128.
//
// Latency-bound at idle clock -> minimize critical-path cycles:
//   * front-batch ALL 32 global loads per thread (full unroll, 4 accumulators)
//   * single __syncthreads(); every warp redundantly reduces the 16 partials
//     from smem (conflict-free), then writes its 2 broadcast rows.

#define B_ 4
#define Q_ 512
#define K_ 512
#define F4 32                    // float4 per feature row
#define THREADS 512
#define REPS 16                  // warps per block
#define ROWS_PER_REP 32          // K rows summed per warp

__global__ void __launch_bounds__(THREADS, 1)
fused_sum_broadcast(const float4* __restrict__ values, float4* __restrict__ out) {
    __shared__ float4 part[REPS][F4];   // 8 KB

    const int b   = blockIdx.x >> 4;    // batch
    const int blk = blockIdx.x & 15;    // output slice within batch
    const int d4  = threadIdx.x & 31;   // float4 index in feature dim
    const int rep = threadIdx.x >> 5;   // warp id = K-slice id

    // Phase 1: sum 32 K-rows. Fully unrolled, 4 independent accumulators ->
    // ptxas front-batches all 32 LDG.128 (one DRAM-latency exposure).
    const float4* p = values + ((size_t)(b * K_ + rep * ROWS_PER_REP)) * F4 + d4;
    float4 a0 = make_float4(0.f,0.f,0.f,0.f);
    float4 a1 = a0, a2 = a0, a3 = a0;
#pragma unroll
    for (int r = 0; r < ROWS_PER_REP; r += 4) {
        float4 v0 = p[(r + 0) * F4];
        float4 v1 = p[(r + 1) * F4];
        float4 v2 = p[(r + 2) * F4];
        float4 v3 = p[(r + 3) * F4];
        a0.x += v0.x; a0.y += v0.y; a0.z += v0.z; a0.w += v0.w;
        a1.x += v1.x; a1.y += v1.y; a1.z += v1.z; a1.w += v1.w;
        a2.x += v2.x; a2.y += v2.y; a2.z += v2.z; a2.w += v2.w;
        a3.x += v3.x; a3.y += v3.y; a3.z += v3.z; a3.w += v3.w;
    }
    float4 acc;
    acc.x = (a0.x + a1.x) + (a2.x + a3.x);
    acc.y = (a0.y + a1.y) + (a2.y + a3.y);
    acc.z = (a0.z + a1.z) + (a2.z + a3.z);
    acc.w = (a0.w + a1.w) + (a2.w + a3.w);
    part[rep][d4] = acc;
    __syncthreads();

    // Phase 2: every warp reduces all 16 partials itself (no warp-0 bottleneck,
    // no second barrier). Pairwise tree keeps the FADD dep chain short.
    float4 s0 = part[0][d4], s1 = part[1][d4];
#pragma unroll
    for (int i = 2; i < REPS; i += 2) {
        float4 v0 = part[i][d4];
        float4 v1 = part[i + 1][d4];
        s0.x += v0.x; s0.y += v0.y; s0.z += v0.z; s0.w += v0.w;
        s1.x += v1.x; s1.y += v1.y; s1.z += v1.z; s1.w += v1.w;
    }
    float4 t;
    t.x = s0.x + s1.x; t.y = s0.y + s1.y;
    t.z = s0.z + s1.z; t.w = s0.w + s1.w;

    // Phase 3: write this warp's 2 broadcast Q-rows (coalesced STG.128).
    float4* ob = out + ((size_t)(b * Q_ + blk * 32 + rep * 2)) * F4 + d4;
    ob[0]  = t;
    ob[F4] = t;
}

extern "C" void kernel_launch(void* const* d_in, const int* in_sizes, int n_in,
                              void* d_out, int out_size) {
    // inputs (metadata order): queries, keys, values, w_score
    const float4* values = (const float4*)d_in[2];
    float4* out = (float4*)d_out;
    fused_sum_broadcast<<<B_ * 16, THREADS>>>(values, out);
}